// round 8
// baseline (speedup 1.0000x reference)
#include <cuda_runtime.h>
#include <cuda_fp16.h>
#include <cstdint>

// ============================================================================
// y = x @ W_binT - rowmean(y),  B=131072, IN=OUT=256.
// Trick 1: fold mean into weights: W' = W_bin - c/256 (EXACT in fp16: n/256).
// Trick 2: single fp16 pass for x (rel err ~2e-4 << 1e-3).
// R8 = R4 structure + OUTPUT-PERMUTED W' rows: within each 64-col warp strip,
//      weight row o = q*16 + ni*2 + b is stored at smem position ni*8 + q*2 + b,
//      so each thread's 16 output values per row are contiguous ->
//      epilogue becomes 32 coalesced STG.128 (was 64 scattered STG.64):
//      4096 -> 1024 L1 wavefronts/tile on the store side.
// ============================================================================

static constexpr int INF    = 256;
static constexpr int OUTF   = 256;
static constexpr int BATCH  = 131072;
static constexpr int MTILE  = 128;
static constexpr int NTILES = BATCH / MTILE;   // 1024
static constexpr int GRID   = 148;
static constexpr int THREADS = 256;

static constexpr int PW = 264;   // W smem pitch (halfs), conflict-free for ldmatrix
static constexpr int PA = 72;    // A smem pitch (halfs), conflict-free for ldmatrix
static constexpr int WBYTES = OUTF * PW * 2;        // 135168
static constexpr int ABYTES = MTILE * PA * 2;       // 18432
static constexpr int SMEM_TOTAL = WBYTES + 2 * ABYTES;  // 172032

__device__ __half g_wprep[OUTF * PW];   // mean-folded W', permuted+padded layout

// ---------------------------------------------------------------------------
// fused prep: one block per input column i; writes W' row o at permuted
// position: strip s=o/64, rem=o%64 = q*16 + m (m = ni*2+b) -> pos
// s*64 + ni*8 + q*2 + b. (Bijective within each strip.)
// ---------------------------------------------------------------------------
__global__ void prep_k(const float* __restrict__ w) {
    __shared__ int red[256];
    const int i = blockIdx.x, t = threadIdx.x;
    const int bin = (w[t * INF + i] > 0.8f) ? 1 : 0;
    red[t] = bin;
    __syncthreads();
    #pragma unroll
    for (int s = 128; s > 0; s >>= 1) {
        if (t < s) red[t] += red[t + s];
        __syncthreads();
    }
    const float v = (float)bin - (float)red[0] * (1.0f / 256.0f);
    const int rem = t & 63;
    const int q  = rem >> 4;
    const int m  = rem & 15;
    const int ni = m >> 1;
    const int b  = m & 1;
    const int pos = (t & ~63) | (ni << 3) | (q << 1) | b;
    g_wprep[pos * PW + i] = __float2half_rn(v);
}

// ---------------------------------------------------------------------------
// main GEMM
// ---------------------------------------------------------------------------
#define MMA_F16(c, a, b0, b1)                                                  \
    asm volatile(                                                              \
        "mma.sync.aligned.m16n8k16.row.col.f32.f16.f16.f32 "                   \
        "{%0,%1,%2,%3},{%4,%5,%6,%7},{%8,%9},{%0,%1,%2,%3};"                   \
        : "+f"((c)[0]), "+f"((c)[1]), "+f"((c)[2]), "+f"((c)[3])               \
        : "r"((a)[0]), "r"((a)[1]), "r"((a)[2]), "r"((a)[3]),                  \
          "r"(b0), "r"(b1))

#define LDSM4(r, addr)                                                         \
    asm volatile("ldmatrix.sync.aligned.m8n8.x4.shared.b16 {%0,%1,%2,%3}, [%4];" \
        : "=r"((r)[0]), "=r"((r)[1]), "=r"((r)[2]), "=r"((r)[3]) : "r"(addr))

__global__ void __launch_bounds__(THREADS, 1)
bgemm_kernel(const float* __restrict__ x, float* __restrict__ out)
{
    extern __shared__ char smem[];
    const int tid  = threadIdx.x;
    const int lane = tid & 31;
    const int wid  = tid >> 5;
    const int wm   = (wid & 1) * 64;   // warp m-offset (2-way)
    const int wn   = (wid >> 1) * 64;  // warp n-offset (4-way)

    // ---- resident W' into smem (whole kernel lifetime)
    {
        const uint4* src = reinterpret_cast<const uint4*>(g_wprep);
        uint4* dst = reinterpret_cast<uint4*>(smem);
        for (int idx = tid; idx < WBYTES / 16; idx += THREADS)
            dst[idx] = src[idx];
    }

    uint32_t sb;
    asm("{ .reg .u64 t; cvta.to.shared.u64 t, %1; cvt.u32.u64 %0, t; }"
        : "=r"(sb) : "l"(smem));
    const uint32_t ABUF[2] = { sb + WBYTES, sb + WBYTES + ABYTES };

    // per-thread ldmatrix source offsets (bytes)
    const uint32_t aoff =
        (uint32_t)((wm + (lane & 15)) * PA + (lane >> 4) * 8) * 2u;
    const uint32_t boff =
        (uint32_t)((wn + ((lane >> 4) & 1) * 8 + (lane & 7)) * PW +
                   ((lane >> 3) & 1) * 8) * 2u;

    // flat-index x mapping: 2048 float4 per 128x64 chunk, 256 threads ->
    // 8 float4/thread: row = (tid>>4) + 16*j, col4 = tid&15.
    const int arow0 = tid >> 4;         // 0..15
    const int acol4 = tid & 15;         // 0..15

    float4 xr[8];

    auto ldg_chunk = [&](int nt, int nc) {
        if (nt < NTILES) {
            const float* gp = x + ((size_t)nt * MTILE + arow0) * INF
                               + nc * 64 + acol4 * 4;
            #pragma unroll
            for (int j = 0; j < 8; ++j) {
                float4 v;
                asm volatile("ld.global.cs.v4.f32 {%0,%1,%2,%3}, [%4];"
                             : "=f"(v.x), "=f"(v.y), "=f"(v.z), "=f"(v.w)
                             : "l"(gp + (size_t)j * 16 * INF));
                xr[j] = v;
            }
        }
    };
    auto sts_chunk = [&](uint32_t ab) {
        const uint32_t base = ab + (uint32_t)(arow0 * PA + acol4 * 4) * 2u;
        #pragma unroll
        for (int j = 0; j < 8; ++j) {
            uint32_t h0, h1;
            asm("cvt.rn.f16x2.f32 %0, %1, %2;" : "=r"(h0) : "f"(xr[j].y), "f"(xr[j].x));
            asm("cvt.rn.f16x2.f32 %0, %1, %2;" : "=r"(h1) : "f"(xr[j].w), "f"(xr[j].z));
            asm volatile("st.shared.v2.b32 [%0], {%1,%2};"
                         :: "r"(base + (uint32_t)(j * 16 * PA) * 2u), "r"(h0), "r"(h1));
        }
    };

    // prologue: chunk0 -> buf0; preload chunk1 regs
    ldg_chunk(blockIdx.x, 0);
    sts_chunk(ABUF[0]);
    ldg_chunk(blockIdx.x, 1);
    __syncthreads();

    for (int tile = blockIdx.x; tile < NTILES; tile += GRID) {
        float acc[4][8][4];
        #pragma unroll
        for (int a = 0; a < 4; ++a)
            #pragma unroll
            for (int b = 0; b < 8; ++b)
                #pragma unroll
                for (int q = 0; q < 4; ++q) acc[a][b][q] = 0.0f;

        #pragma unroll
        for (int ch = 0; ch < 4; ++ch) {
            // STS chunk ch+1 (regs already loaded) into the other buffer
            const bool has_next = !(ch == 3 && tile + GRID >= NTILES);
            if (has_next) sts_chunk(ABUF[(ch + 1) & 1]);

            // prefetch regs for chunk ch+2
            {
                int nt = tile, nc = ch + 2;
                if (nc >= 4) { nc -= 4; nt += GRID; }
                ldg_chunk(nt, nc);
            }

            // MMA over chunk ch (4 k16-steps) from buf[ch&1]
            const uint32_t AB  = ABUF[ch & 1];
            const uint32_t bko = (uint32_t)(ch * 64) * 2u;
            #pragma unroll
            for (int ks = 0; ks < 4; ++ks) {
                const uint32_t kb2 = (uint32_t)(ks * 16) * 2u;
                uint32_t bfr[4][4];
                #pragma unroll
                for (int np = 0; np < 4; ++np)
                    LDSM4(bfr[np], sb + boff + (uint32_t)(np * 16 * PW * 2) + bko + kb2);
                uint32_t af[4][4];
                #pragma unroll
                for (int mi = 0; mi < 4; ++mi)
                    LDSM4(af[mi], AB + aoff + (uint32_t)(mi * 16 * PA * 2) + kb2);
                #pragma unroll
                for (int mi = 0; mi < 4; ++mi)
                    #pragma unroll
                    for (int ni = 0; ni < 8; ++ni)
                        MMA_F16(acc[mi][ni], af[mi],
                                bfr[ni >> 1][(ni & 1) * 2],
                                bfr[ni >> 1][(ni & 1) * 2 + 1]);
            }
            __syncthreads();
        }

        // ---- epilogue: permuted layout -> each thread owns 16 contiguous
        //      output cols per row: 4x STG.128, fully coalesced.
        const int g   = lane >> 2;          // row group 0..7
        const int qcol = wn + (lane & 3) * 16;
        #pragma unroll
        for (int mi = 0; mi < 4; ++mi) {
            const size_t rbase = (size_t)(tile * MTILE + wm + mi * 16);
            float* p0 = out + (rbase + g)     * OUTF + qcol;
            float* p1 = out + (rbase + g + 8) * OUTF + qcol;
            #pragma unroll
            for (int j = 0; j < 4; ++j) {
                asm volatile("st.global.cs.v4.f32 [%0], {%1,%2,%3,%4};"
                             :: "l"(p0 + j * 4),
                                "f"(acc[mi][2*j][0]), "f"(acc[mi][2*j][1]),
                                "f"(acc[mi][2*j+1][0]), "f"(acc[mi][2*j+1][1]));
                asm volatile("st.global.cs.v4.f32 [%0], {%1,%2,%3,%4};"
                             :: "l"(p1 + j * 4),
                                "f"(acc[mi][2*j][2]), "f"(acc[mi][2*j][3]),
                                "f"(acc[mi][2*j+1][2]), "f"(acc[mi][2*j+1][3]));
            }
        }
    }
}

// ---------------------------------------------------------------------------
extern "C" void kernel_launch(void* const* d_in, const int* in_sizes, int n_in,
                              void* d_out, int out_size) {
    const float* x = (const float*)d_in[0];
    const float* w = (const float*)d_in[1];
    if (n_in >= 2 && in_sizes[0] < in_sizes[1]) {  // defensive: x is the big one
        const float* t = x; x = w; w = t;
    }
    float* out = (float*)d_out;

    prep_k<<<256, 256>>>(w);

    cudaFuncSetAttribute(bgemm_kernel,
                         cudaFuncAttributeMaxDynamicSharedMemorySize, SMEM_TOTAL);
    bgemm_kernel<<<GRID, THREADS, SMEM_TOTAL>>>(x, out);
}

// round 9
// speedup vs baseline: 1.2115x; 1.2115x over previous
#include <cuda_runtime.h>
#include <cuda_fp16.h>
#include <cstdint>

// ============================================================================
// y = x @ W_binT - rowmean(y),  B=131072, IN=OUT=256.
// Trick 1: fold mean into weights: W' = W_bin - c/256 (EXACT in fp16: n/256).
// Trick 2: single fp16 pass for x (rel err ~2e-4 << 1e-3).
// R9 = R4 core (unchanged) + sector-aligned permuted epilogue:
//      W' strip rows permuted s = j*16 + (e>>1)*8 + q*2 + (e&1) so each
//      STG.128 has lanes 0-3 writing 64B CONTIGUOUS per row (full sectors;
//      R8's version was half-sector RMW). STG: 16384x64b -> 8192x128b.
// ============================================================================

static constexpr int INF    = 256;
static constexpr int OUTF   = 256;
static constexpr int BATCH  = 131072;
static constexpr int MTILE  = 128;
static constexpr int NTILES = BATCH / MTILE;   // 1024
static constexpr int GRID   = 148;
static constexpr int THREADS = 256;

static constexpr int PW = 264;   // W smem pitch (halfs), conflict-free for ldmatrix
static constexpr int PA = 72;    // A smem pitch (halfs), conflict-free for ldmatrix
static constexpr int WBYTES = OUTF * PW * 2;        // 135168
static constexpr int ABYTES = MTILE * PA * 2;       // 18432
static constexpr int SMEM_TOTAL = WBYTES + 2 * ABYTES;  // 172032

__device__ __half g_wprep[OUTF * PW];   // mean-folded W', permuted+padded layout

// ---------------------------------------------------------------------------
// fused prep: one block per input column i. Weight row o is stored at strip
// position s so that the epilogue's thread-register groups map to contiguous
// output columns:  rem=o&63: j=rem>>4, q=(rem>>2)&3, e=rem&3
//                  s = j*16 + (e>>1)*8 + q*2 + (e&1)
// (acc[mi][ni][b] lives at strip pos ni*8+q*2+b; with ni=j*2+(e>>1), b=e&1
//  this lands logical col o at exactly j*16+q*4+e. Bijective.)
// ---------------------------------------------------------------------------
__global__ void prep_k(const float* __restrict__ w) {
    __shared__ int red[256];
    const int i = blockIdx.x, t = threadIdx.x;
    const int bin = (w[t * INF + i] > 0.8f) ? 1 : 0;
    red[t] = bin;
    __syncthreads();
    #pragma unroll
    for (int s = 128; s > 0; s >>= 1) {
        if (t < s) red[t] += red[t + s];
        __syncthreads();
    }
    const float v = (float)bin - (float)red[0] * (1.0f / 256.0f);
    const int rem = t & 63;
    const int j = rem >> 4;
    const int q = (rem >> 2) & 3;
    const int e = rem & 3;
    const int s = j * 16 + (e >> 1) * 8 + q * 2 + (e & 1);
    const int pos = (t & ~63) | s;
    g_wprep[pos * PW + i] = __float2half_rn(v);
}

// ---------------------------------------------------------------------------
// main GEMM
// ---------------------------------------------------------------------------
#define MMA_F16(c, a, b0, b1)                                                  \
    asm volatile(                                                              \
        "mma.sync.aligned.m16n8k16.row.col.f32.f16.f16.f32 "                   \
        "{%0,%1,%2,%3},{%4,%5,%6,%7},{%8,%9},{%0,%1,%2,%3};"                   \
        : "+f"((c)[0]), "+f"((c)[1]), "+f"((c)[2]), "+f"((c)[3])               \
        : "r"((a)[0]), "r"((a)[1]), "r"((a)[2]), "r"((a)[3]),                  \
          "r"(b0), "r"(b1))

#define LDSM4(r, addr)                                                         \
    asm volatile("ldmatrix.sync.aligned.m8n8.x4.shared.b16 {%0,%1,%2,%3}, [%4];" \
        : "=r"((r)[0]), "=r"((r)[1]), "=r"((r)[2]), "=r"((r)[3]) : "r"(addr))

__global__ void __launch_bounds__(THREADS, 1)
bgemm_kernel(const float* __restrict__ x, float* __restrict__ out)
{
    extern __shared__ char smem[];
    const int tid  = threadIdx.x;
    const int lane = tid & 31;
    const int wid  = tid >> 5;
    const int wm   = (wid & 1) * 64;   // warp m-offset (2-way)
    const int wn   = (wid >> 1) * 64;  // warp n-offset (4-way)

    // ---- resident W' into smem (whole kernel lifetime)
    {
        const uint4* src = reinterpret_cast<const uint4*>(g_wprep);
        uint4* dst = reinterpret_cast<uint4*>(smem);
        for (int idx = tid; idx < WBYTES / 16; idx += THREADS)
            dst[idx] = src[idx];
    }

    uint32_t sb;
    asm("{ .reg .u64 t; cvta.to.shared.u64 t, %1; cvt.u32.u64 %0, t; }"
        : "=r"(sb) : "l"(smem));
    const uint32_t ABUF[2] = { sb + WBYTES, sb + WBYTES + ABYTES };

    // per-thread ldmatrix source offsets (bytes)
    const uint32_t aoff =
        (uint32_t)((wm + (lane & 15)) * PA + (lane >> 4) * 8) * 2u;
    const uint32_t boff =
        (uint32_t)((wn + ((lane >> 4) & 1) * 8 + (lane & 7)) * PW +
                   ((lane >> 3) & 1) * 8) * 2u;

    // flat-index x mapping: 2048 float4 per 128x64 chunk, 256 threads ->
    // 8 float4/thread: row = (tid>>4) + 16*j, col4 = tid&15.
    const int arow0 = tid >> 4;         // 0..15
    const int acol4 = tid & 15;         // 0..15

    float4 xr[8];

    auto ldg_chunk = [&](int nt, int nc) {
        if (nt < NTILES) {
            const float* gp = x + ((size_t)nt * MTILE + arow0) * INF
                               + nc * 64 + acol4 * 4;
            #pragma unroll
            for (int j = 0; j < 8; ++j) {
                float4 v;
                asm volatile("ld.global.cs.v4.f32 {%0,%1,%2,%3}, [%4];"
                             : "=f"(v.x), "=f"(v.y), "=f"(v.z), "=f"(v.w)
                             : "l"(gp + (size_t)j * 16 * INF));
                xr[j] = v;
            }
        }
    };
    auto sts_chunk = [&](uint32_t ab) {
        const uint32_t base = ab + (uint32_t)(arow0 * PA + acol4 * 4) * 2u;
        #pragma unroll
        for (int j = 0; j < 8; ++j) {
            uint32_t h0, h1;
            asm("cvt.rn.f16x2.f32 %0, %1, %2;" : "=r"(h0) : "f"(xr[j].y), "f"(xr[j].x));
            asm("cvt.rn.f16x2.f32 %0, %1, %2;" : "=r"(h1) : "f"(xr[j].w), "f"(xr[j].z));
            asm volatile("st.shared.v2.b32 [%0], {%1,%2};"
                         :: "r"(base + (uint32_t)(j * 16 * PA) * 2u), "r"(h0), "r"(h1));
        }
    };

    // prologue: chunk0 -> buf0; preload chunk1 regs
    ldg_chunk(blockIdx.x, 0);
    sts_chunk(ABUF[0]);
    ldg_chunk(blockIdx.x, 1);
    __syncthreads();

    for (int tile = blockIdx.x; tile < NTILES; tile += GRID) {
        float acc[4][8][4];
        #pragma unroll
        for (int a = 0; a < 4; ++a)
            #pragma unroll
            for (int b = 0; b < 8; ++b)
                #pragma unroll
                for (int q = 0; q < 4; ++q) acc[a][b][q] = 0.0f;

        #pragma unroll
        for (int ch = 0; ch < 4; ++ch) {
            // STS chunk ch+1 (regs already loaded) into the other buffer
            const bool has_next = !(ch == 3 && tile + GRID >= NTILES);
            if (has_next) sts_chunk(ABUF[(ch + 1) & 1]);

            // prefetch regs for chunk ch+2
            {
                int nt = tile, nc = ch + 2;
                if (nc >= 4) { nc -= 4; nt += GRID; }
                ldg_chunk(nt, nc);
            }

            // MMA over chunk ch (4 k16-steps) from buf[ch&1]
            const uint32_t AB  = ABUF[ch & 1];
            const uint32_t bko = (uint32_t)(ch * 64) * 2u;
            #pragma unroll
            for (int ks = 0; ks < 4; ++ks) {
                const uint32_t kb2 = (uint32_t)(ks * 16) * 2u;
                uint32_t bfr[4][4];
                #pragma unroll
                for (int np = 0; np < 4; ++np)
                    LDSM4(bfr[np], sb + boff + (uint32_t)(np * 16 * PW * 2) + bko + kb2);
                uint32_t af[4][4];
                #pragma unroll
                for (int mi = 0; mi < 4; ++mi)
                    LDSM4(af[mi], AB + aoff + (uint32_t)(mi * 16 * PA * 2) + kb2);
                #pragma unroll
                for (int mi = 0; mi < 4; ++mi)
                    #pragma unroll
                    for (int ni = 0; ni < 8; ++ni)
                        MMA_F16(acc[mi][ni], af[mi],
                                bfr[ni >> 1][(ni & 1) * 2],
                                bfr[ni >> 1][(ni & 1) * 2 + 1]);
            }
            __syncthreads();
        }

        // ---- epilogue: sector-aligned permuted stores.
        // lane q=lane&3, g=lane>>2. Store j covers cols wn + j*16 + q*4..+3:
        // lanes 0-3 of a row group write 64B CONTIGUOUS (full sectors).
        const int g = lane >> 2;
        const int q = lane & 3;
        #pragma unroll
        for (int mi = 0; mi < 4; ++mi) {
            const size_t rbase = (size_t)(tile * MTILE + wm + mi * 16);
            float* p0 = out + (rbase + g)     * OUTF + wn + q * 4;
            float* p1 = out + (rbase + g + 8) * OUTF + wn + q * 4;
            #pragma unroll
            for (int j = 0; j < 4; ++j) {
                asm volatile("st.global.cs.v4.f32 [%0], {%1,%2,%3,%4};"
                             :: "l"(p0 + j * 16),
                                "f"(acc[mi][2*j][0]), "f"(acc[mi][2*j][1]),
                                "f"(acc[mi][2*j+1][0]), "f"(acc[mi][2*j+1][1]));
                asm volatile("st.global.cs.v4.f32 [%0], {%1,%2,%3,%4};"
                             :: "l"(p1 + j * 16),
                                "f"(acc[mi][2*j][2]), "f"(acc[mi][2*j][3]),
                                "f"(acc[mi][2*j+1][2]), "f"(acc[mi][2*j+1][3]));
            }
        }
    }
}

// ---------------------------------------------------------------------------
extern "C" void kernel_launch(void* const* d_in, const int* in_sizes, int n_in,
                              void* d_out, int out_size) {
    const float* x = (const float*)d_in[0];
    const float* w = (const float*)d_in[1];
    if (n_in >= 2 && in_sizes[0] < in_sizes[1]) {  // defensive: x is the big one
        const float* t = x; x = w; w = t;
    }
    float* out = (float*)d_out;

    prep_k<<<256, 256>>>(w);

    cudaFuncSetAttribute(bgemm_kernel,
                         cudaFuncAttributeMaxDynamicSharedMemorySize, SMEM_TOTAL);
    bgemm_kernel<<<GRID, THREADS, SMEM_TOTAL>>>(x, out);
}